// round 10
// baseline (speedup 1.0000x reference)
#include <cuda_runtime.h>
#include <cstdint>

// out[i] = x[i] + 42.0f, 8192*4096 fp32. Converged HBM-streaming kernel.
// R10 micro-variant of the thrice-reproduced best (43.8/43.8/43.5us):
// loads use .cg (L2-only, no L1 allocate) instead of .cs — removes the
// pointless L1tex allocate path on a zero-reuse stream. Stores stay .cs.

constexpr int TPB = 256;
constexpr int UNR = 8;                       // float4 per thread
constexpr int TILE = TPB * UNR;              // float4 per block = 2048

__global__ void __launch_bounds__(TPB) add42_exact(const float4* __restrict__ in,
                                                   float4* __restrict__ out) {
    const unsigned base = blockIdx.x * TILE + threadIdx.x;
    float4 v[UNR];
    #pragma unroll
    for (int k = 0; k < UNR; k++)
        v[k] = __ldcg(&in[base + k * TPB]);   // L2-only load, bypass L1
    #pragma unroll
    for (int k = 0; k < UNR; k++) {
        v[k].x += 42.0f; v[k].y += 42.0f; v[k].z += 42.0f; v[k].w += 42.0f;
        __stcs(&out[base + k * TPB], v[k]);   // streaming store
    }
}

// Grid-stride float4 fallback for remainder after exact tiles.
__global__ void __launch_bounds__(TPB) add42_vec4_gs(const float4* __restrict__ in,
                                                     float4* __restrict__ out,
                                                     long long start, long long n4) {
    const long long stride = (long long)gridDim.x * blockDim.x;
    for (long long i = start + (long long)blockIdx.x * blockDim.x + threadIdx.x;
         i < n4; i += stride) {
        float4 a = __ldcg(&in[i]);
        a.x += 42.0f; a.y += 42.0f; a.z += 42.0f; a.w += 42.0f;
        __stcs(&out[i], a);
    }
}

__global__ void add42_tail(const float* __restrict__ in, float* __restrict__ out,
                           long long start, long long n) {
    long long i = start + (long long)blockIdx.x * blockDim.x + threadIdx.x;
    if (i < n) out[i] = in[i] + 42.0f;
}

extern "C" void kernel_launch(void* const* d_in, const int* in_sizes, int n_in,
                              void* d_out, int out_size) {
    const float* x = (const float*)d_in[0];
    float* out = (float*)d_out;
    const long long n = (long long)in_sizes[0];

    const long long n4 = n / 4;
    const long long exact_blocks = n4 / TILE;           // 4096 for 8192x4096
    if (exact_blocks > 0) {
        add42_exact<<<(int)exact_blocks, TPB>>>((const float4*)x, (float4*)out);
    }
    const long long vec_rem_start = exact_blocks * (long long)TILE;
    if (vec_rem_start < n4) {
        long long rem = n4 - vec_rem_start;
        int blocks = (int)((rem + TPB - 1) / TPB);
        if (blocks > 152 * 8) blocks = 152 * 8;
        add42_vec4_gs<<<blocks, TPB>>>((const float4*)x, (float4*)out,
                                       vec_rem_start, n4);
    }
    const long long tail_start = n4 * 4;
    if (tail_start < n) {
        long long tail = n - tail_start;
        int blocks = (int)((tail + 127) / 128);
        add42_tail<<<blocks, 128>>>(x, out, tail_start, n);
    }
}

// round 11
// speedup vs baseline: 1.0280x; 1.0280x over previous
#include <cuda_runtime.h>
#include <cstdint>

// out[i] = x[i] + 42.0f, 8192*4096 fp32. FINAL kernel.
// Config: float4 x8 per thread, exact 32KB tiles, TPB=256, .cs load/store.
// Reproduced at 43.8/43.8/43.5us e2e (best of a 43.5-45.8us band across a
// 10-round sweep of vector width, MLP, occupancy, cache ops, L2 eviction
// policies, and burst phasing — all neutral). Steady state moves the
// mandatory 268MB/replay at ~7.3TB/s effective (~90% of 8TB/s HBM3e spec):
// the mixed read/write DRAM ceiling. Remaining ~6us is graph-replay overhead.

constexpr int TPB = 256;
constexpr int UNR = 8;                       // float4 per thread
constexpr int TILE = TPB * UNR;              // float4 per block = 2048

__global__ void __launch_bounds__(TPB) add42_exact(const float4* __restrict__ in,
                                                   float4* __restrict__ out) {
    const unsigned base = blockIdx.x * TILE + threadIdx.x;
    float4 v[UNR];
    #pragma unroll
    for (int k = 0; k < UNR; k++)
        v[k] = __ldcs(&in[base + k * TPB]);   // evict-first: no reuse
    #pragma unroll
    for (int k = 0; k < UNR; k++) {
        v[k].x += 42.0f; v[k].y += 42.0f; v[k].z += 42.0f; v[k].w += 42.0f;
        __stcs(&out[base + k * TPB], v[k]);   // streaming store
    }
}

// Grid-stride float4 fallback for remainder after exact tiles.
__global__ void __launch_bounds__(TPB) add42_vec4_gs(const float4* __restrict__ in,
                                                     float4* __restrict__ out,
                                                     long long start, long long n4) {
    const long long stride = (long long)gridDim.x * blockDim.x;
    for (long long i = start + (long long)blockIdx.x * blockDim.x + threadIdx.x;
         i < n4; i += stride) {
        float4 a = __ldcs(&in[i]);
        a.x += 42.0f; a.y += 42.0f; a.z += 42.0f; a.w += 42.0f;
        __stcs(&out[i], a);
    }
}

__global__ void add42_tail(const float* __restrict__ in, float* __restrict__ out,
                           long long start, long long n) {
    long long i = start + (long long)blockIdx.x * blockDim.x + threadIdx.x;
    if (i < n) out[i] = in[i] + 42.0f;
}

extern "C" void kernel_launch(void* const* d_in, const int* in_sizes, int n_in,
                              void* d_out, int out_size) {
    const float* x = (const float*)d_in[0];
    float* out = (float*)d_out;
    const long long n = (long long)in_sizes[0];

    const long long n4 = n / 4;
    const long long exact_blocks = n4 / TILE;           // 4096 for 8192x4096
    if (exact_blocks > 0) {
        add42_exact<<<(int)exact_blocks, TPB>>>((const float4*)x, (float4*)out);
    }
    const long long vec_rem_start = exact_blocks * (long long)TILE;
    if (vec_rem_start < n4) {
        long long rem = n4 - vec_rem_start;
        int blocks = (int)((rem + TPB - 1) / TPB);
        if (blocks > 152 * 8) blocks = 152 * 8;
        add42_vec4_gs<<<blocks, TPB>>>((const float4*)x, (float4*)out,
                                       vec_rem_start, n4);
    }
    const long long tail_start = n4 * 4;
    if (tail_start < n) {
        long long tail = n - tail_start;
        int blocks = (int)((tail + 127) / 128);
        add42_tail<<<blocks, 128>>>(x, out, tail_start, n);
    }
}